// round 3
// baseline (speedup 1.0000x reference)
#include <cuda_runtime.h>
#include <cuda_bf16.h>
#include <cstdint>

#define NTOK   4096
#define HDIM   4096
#define VOCAB  32000
#define M_TILE 128
#define N_TILE 128
#define KC     32
#define STAGES 4
#define KITERS (HDIM / KC)          // 128
#define NVT    (VOCAB / N_TILE)     // 250
#define ROWB   80                   // padded row bytes (32 bf16 = 64B + 16 pad)
#define STAGE_BYTES (2 * M_TILE * ROWB)   // A + B = 20480
#define SMEM_DYN (STAGES * STAGE_BYTES)   // 81920

__device__ __nv_bfloat16 g_w_bf16[(size_t)VOCAB * HDIM];
__device__ __nv_bfloat16 g_x_bf16[(size_t)NTOK * HDIM];
__device__ float g_partial[(size_t)NVT * NTOK];
__device__ float g_tgt[NTOK];
__device__ float g_bsum[32];
__device__ int   g_bcnt[32];

__device__ __forceinline__ uint32_t smem_u32(const void* p) {
    uint32_t a;
    asm("{ .reg .u64 t; cvta.to.shared.u64 t, %1; cvt.u32.u64 %0, t; }" : "=r"(a) : "l"(p));
    return a;
}
__device__ __forceinline__ void cp16(uint32_t dst, const void* src) {
    asm volatile("cp.async.cg.shared.global [%0], [%1], 16;" :: "r"(dst), "l"(src) : "memory");
}
__device__ __forceinline__ void ldsm4(uint32_t addr, uint32_t& r0, uint32_t& r1, uint32_t& r2, uint32_t& r3) {
    asm volatile("ldmatrix.sync.aligned.m8n8.x4.shared.b16 {%0,%1,%2,%3}, [%4];"
                 : "=r"(r0), "=r"(r1), "=r"(r2), "=r"(r3) : "r"(addr));
}
__device__ __forceinline__ void mma16816(float* d, const uint32_t* a, uint32_t b0, uint32_t b1) {
    asm volatile("mma.sync.aligned.m16n8k16.row.col.f32.bf16.bf16.f32 "
                 "{%0,%1,%2,%3}, {%4,%5,%6,%7}, {%8,%9}, {%0,%1,%2,%3};"
                 : "+f"(d[0]), "+f"(d[1]), "+f"(d[2]), "+f"(d[3])
                 : "r"(a[0]), "r"(a[1]), "r"(a[2]), "r"(a[3]), "r"(b0), "r"(b1));
}

// -------- kernel 1: fp32 -> bf16 --------
__global__ void conv_kernel(const float4* __restrict__ in, uint2* __restrict__ out, long n4) {
    long i = (long)blockIdx.x * blockDim.x + threadIdx.x;
    long stride = (long)gridDim.x * blockDim.x;
    for (; i < n4; i += stride) {
        float4 v = in[i];
        __nv_bfloat162 lo = __floats2bfloat162_rn(v.x, v.y);
        __nv_bfloat162 hi = __floats2bfloat162_rn(v.z, v.w);
        uint2 o;
        o.x = *reinterpret_cast<uint32_t*>(&lo);
        o.y = *reinterpret_cast<uint32_t*>(&hi);
        out[i] = o;
    }
}

// -------- kernel 2: bf16 mma.sync GEMM + fused exp-sum epilogue --------
__global__ void __launch_bounds__(256, 2)
fce_gemm_kernel(const float* __restrict__ bias) {
    extern __shared__ __align__(16) char smem[];
    __shared__ float redS[2][M_TILE];
    __shared__ float biasS[N_TILE];

    const uint32_t sb = smem_u32(smem);
    const int tid = threadIdx.x;
    const int lane = tid & 31;
    const int wid = tid >> 5;
    const int warp_m = wid & 3;            // 4 warps in M -> 32 rows each
    const int warp_n = wid >> 2;           // 2 warps in N -> 64 cols each
    const int m_blk = blockIdx.x;          // fast-varying: share W tile in L2
    const int n_blk = blockIdx.y;
    const int rowy = m_blk * M_TILE;
    const int coly = n_blk * N_TILE;

    const __nv_bfloat16* __restrict__ gx = g_x_bf16;
    const __nv_bfloat16* __restrict__ gw = g_w_bf16;

    // per-thread load slots: 512 16B-chunks per tile, 2 per thread per tile
    const int c0 = tid, c1 = tid + 256;
    const int r0 = c0 >> 2, k0 = c0 & 3;
    const int r1 = c1 >> 2, k1 = c1 & 3;

    float acc[2][8][4];
#pragma unroll
    for (int i = 0; i < 2; i++)
#pragma unroll
        for (int j = 0; j < 8; j++)
#pragma unroll
            for (int k = 0; k < 4; k++) acc[i][j][k] = 0.f;

    auto load_stage = [&](int st, int it) {
        const uint32_t sA = sb + st * STAGE_BYTES;
        const uint32_t sB = sA + M_TILE * ROWB;
        const long kbase = (long)it * KC;
        cp16(sA + r0 * ROWB + k0 * 16, gx + ((long)(rowy + r0) * HDIM + kbase + k0 * 8));
        cp16(sA + r1 * ROWB + k1 * 16, gx + ((long)(rowy + r1) * HDIM + kbase + k1 * 8));
        cp16(sB + r0 * ROWB + k0 * 16, gw + ((long)(coly + r0) * HDIM + kbase + k0 * 8));
        cp16(sB + r1 * ROWB + k1 * 16, gw + ((long)(coly + r1) * HDIM + kbase + k1 * 8));
    };

#pragma unroll
    for (int s = 0; s < STAGES - 1; s++) {
        load_stage(s, s);
        asm volatile("cp.async.commit_group;" ::: "memory");
    }

    const int lrow = lane & 15;
    const int lhalf = (lane >> 4) * 16;

    for (int it = 0; it < KITERS; ++it) {
        asm volatile("cp.async.wait_group 2;" ::: "memory");
        __syncthreads();
        const int pf = it + STAGES - 1;
        if (pf < KITERS) load_stage(pf & (STAGES - 1), pf);
        asm volatile("cp.async.commit_group;" ::: "memory");

        const int st = it & (STAGES - 1);
        const uint32_t sA = sb + st * STAGE_BYTES;
        const uint32_t sB = sA + M_TILE * ROWB;
#pragma unroll
        for (int ks = 0; ks < 2; ks++) {
            const int kb = ks * 32;  // bytes into row
            uint32_t a[2][4], b[4][4];
#pragma unroll
            for (int mi = 0; mi < 2; mi++)
                ldsm4(sA + (warp_m * 32 + mi * 16 + lrow) * ROWB + lhalf + kb,
                      a[mi][0], a[mi][1], a[mi][2], a[mi][3]);
#pragma unroll
            for (int nj = 0; nj < 4; nj++)
                ldsm4(sB + (warp_n * 64 + nj * 16 + lrow) * ROWB + lhalf + kb,
                      b[nj][0], b[nj][1], b[nj][2], b[nj][3]);
#pragma unroll
            for (int mi = 0; mi < 2; mi++)
#pragma unroll
                for (int ni = 0; ni < 8; ni++)
                    mma16816(acc[mi][ni], a[mi], b[ni >> 1][ni & 1], b[ni >> 1][(ni & 1) + 2]);
        }
        __syncthreads();
    }

    // ---- epilogue: sum exp(logit + bias) per row ----
    for (int i = tid; i < N_TILE; i += 256) biasS[i] = __ldg(&bias[coly + i]);
    __syncthreads();

    const int gid = lane >> 2, quad = lane & 3;
    float rs[2][2] = {{0.f, 0.f}, {0.f, 0.f}};
#pragma unroll
    for (int mi = 0; mi < 2; mi++)
#pragma unroll
        for (int ni = 0; ni < 8; ni++) {
            const int col = warp_n * 64 + ni * 8 + quad * 2;
            const float b0 = biasS[col], b1 = biasS[col + 1];
            rs[mi][0] += __expf(acc[mi][ni][0] + b0) + __expf(acc[mi][ni][1] + b1);
            rs[mi][1] += __expf(acc[mi][ni][2] + b0) + __expf(acc[mi][ni][3] + b1);
        }
#pragma unroll
    for (int off = 1; off <= 2; off <<= 1) {
#pragma unroll
        for (int mi = 0; mi < 2; mi++) {
            rs[mi][0] += __shfl_xor_sync(~0u, rs[mi][0], off);
            rs[mi][1] += __shfl_xor_sync(~0u, rs[mi][1], off);
        }
    }
    if (quad == 0) {
#pragma unroll
        for (int mi = 0; mi < 2; mi++) {
            redS[warp_n][warp_m * 32 + mi * 16 + gid] = rs[mi][0];
            redS[warp_n][warp_m * 32 + mi * 16 + 8 + gid] = rs[mi][1];
        }
    }
    __syncthreads();
    if (tid < M_TILE)
        g_partial[(size_t)n_blk * NTOK + rowy + tid] = redS[0][tid] + redS[1][tid];
}

// -------- kernel 3: exact fp32 target logits --------
__device__ __forceinline__ bool tgt_is_i64(const int* p) {
    int bad = 0;
#pragma unroll
    for (int k = 0; k < 32; k++) {
        int v = p[2 * k + 1];
        bad |= (v != 0 && v != -1);
    }
    return !bad;
}
__global__ void tgt_kernel(const float* __restrict__ x, const float* __restrict__ w,
                           const int* __restrict__ tgt, const float* __restrict__ bias) {
    __shared__ float red[4];
    const int n = blockIdx.x, tid = threadIdx.x;
    const bool i64 = tgt_is_i64(tgt);
    const long long t = i64 ? ((const long long*)tgt)[n] : (long long)tgt[n];
    if (t < 0 || t >= VOCAB) { if (tid == 0) g_tgt[n] = 0.f; return; }
    const float4* xa = (const float4*)(x + (size_t)n * HDIM);
    const float4* wa = (const float4*)(w + (size_t)t * HDIM);
    float s = 0.f;
#pragma unroll
    for (int i = 0; i < 8; i++) {
        float4 a = xa[tid + 128 * i];
        float4 b = wa[tid + 128 * i];
        s += a.x * b.x + a.y * b.y + a.z * b.z + a.w * b.w;
    }
    for (int o = 16; o; o >>= 1) s += __shfl_xor_sync(~0u, s, o);
    if ((tid & 31) == 0) red[tid >> 5] = s;
    __syncthreads();
    if (tid == 0) g_tgt[n] = red[0] + red[1] + red[2] + red[3] + __ldg(&bias[t]);
}

// -------- kernels 4/5: deterministic reduction --------
__global__ void reduce1_kernel(const int* __restrict__ tgt) {
    const int tid = threadIdx.x;
    const int row = blockIdx.x * 128 + tid;
    const bool i64 = tgt_is_i64(tgt);
    const long long t = i64 ? ((const long long*)tgt)[row] : (long long)tgt[row];
    float rsum = 0.f;
    for (int c = 0; c < NVT; c++) rsum += g_partial[(size_t)c * NTOK + row];
    float nll = 0.f;
    int v = 0;
    if (t != -100LL) { nll = logf(rsum) - g_tgt[row]; v = 1; }
    for (int o = 16; o; o >>= 1) {
        nll += __shfl_xor_sync(~0u, nll, o);
        v   += __shfl_xor_sync(~0u, v, o);
    }
    __shared__ float fs[4];
    __shared__ int iv[4];
    if ((tid & 31) == 0) { fs[tid >> 5] = nll; iv[tid >> 5] = v; }
    __syncthreads();
    if (tid == 0) {
        g_bsum[blockIdx.x] = fs[0] + fs[1] + fs[2] + fs[3];
        g_bcnt[blockIdx.x] = iv[0] + iv[1] + iv[2] + iv[3];
    }
}
__global__ void reduce2_kernel(float* __restrict__ out) {
    const int tid = threadIdx.x;
    float s = g_bsum[tid];
    int c = g_bcnt[tid];
    for (int o = 16; o; o >>= 1) {
        s += __shfl_xor_sync(~0u, s, o);
        c += __shfl_xor_sync(~0u, c, o);
    }
    if (tid == 0) out[0] = s / (float)(c > 0 ? c : 1);
}

// -------- host --------
extern "C" void kernel_launch(void* const* d_in, const int* in_sizes, int n_in,
                              void* d_out, int out_size) {
    const float* w = nullptr;
    const float* x = nullptr;
    const float* bias = nullptr;
    const int* tgt = nullptr;
    for (int i = 0; i < n_in; i++) {
        switch (in_sizes[i]) {
            case 131072000: w = (const float*)d_in[i]; break;
            case 16777216:  x = (const float*)d_in[i]; break;
            case 4096:      tgt = (const int*)d_in[i]; break;
            case 32000:     bias = (const float*)d_in[i]; break;
            default: break;
        }
    }
    if (!w || !x || !tgt || !bias) return;

    void* wbf = nullptr; void* xbf = nullptr;
    cudaGetSymbolAddress(&wbf, g_w_bf16);
    cudaGetSymbolAddress(&xbf, g_x_bf16);

    cudaFuncSetAttribute(fce_gemm_kernel, cudaFuncAttributeMaxDynamicSharedMemorySize, SMEM_DYN);

    conv_kernel<<<4096, 256>>>((const float4*)w, (uint2*)wbf, (long)VOCAB * HDIM / 4);
    conv_kernel<<<1024, 256>>>((const float4*)x, (uint2*)xbf, (long)NTOK * HDIM / 4);
    tgt_kernel<<<NTOK, 128>>>(x, w, tgt, bias);
    fce_gemm_kernel<<<dim3(NTOK / M_TILE, NVT), 256, SMEM_DYN>>>(bias);
    reduce1_kernel<<<32, 128>>>(tgt);
    reduce2_kernel<<<1, 32>>>((float*)d_out);
}